// round 10
// baseline (speedup 1.0000x reference)
#include <cuda_runtime.h>
#include <cuda_fp16.h>
#include <mma.h>

// Problem constants (fixed by the dataset)
#define T_STEPS 8
#define N_NODES 50000
#define E_EDGES 800000
#define DD 64
#define TOTAL_ROWS (T_STEPS * N_NODES)    // 400000
#define NPART ((N_NODES + 255) / 256)     // 196 scan blocks

// -------- scratch (static __device__ arrays; no allocation allowed) --------
// y laid out [node][t][64]  -> node stride = 1024 B; 8 t-rows contiguous.
__device__ __half g_y[(size_t)N_NODES * T_STEPS * DD];   // 51.2 MB
__device__ int    g_offsets[N_NODES + 1];
__device__ int    g_mid[N_NODES];       // off + #(tact<4)
__device__ int    g_curA[N_NODES];      // cursor for tact<4 region
__device__ int    g_curB[N_NODES];      // cursor for 4<=tact<8 region
__device__ int2   g_edges[E_EDGES];     // ((src<<10)|tact, w bits); dead edges dropped

struct ScanState {
    int counts[N_NODES];   // #(tact<8) per dst   (re-zeroed by gather_kernel)
    int cntA[N_NODES];     // #(tact<4) per dst   (re-zeroed by gather_kernel)
    int agg[NPART];
    int pre[NPART];
    int flag[NPART];       // 0=invalid, 1=aggregate, 2=prefix (re-zeroed by gather)
};
__device__ ScanState g_ss;

// ---------------------------------------------------------------------------
__device__ __forceinline__ int compute_tact(float et, const float* __restrict__ node_time) {
    int tact = 0;
    #pragma unroll
    for (int t = 0; t < T_STEPS; t++) tact += (__ldg(&node_time[t]) < et) ? 1 : 0;
    return tact;
}

// ---------------------------------------------------------------------------
// Kernel 1: y = x @ W via wmma, 256 rows/block (1563 blocks), fused counts.
__global__ __launch_bounds__(256) void gemm_count_kernel(const float* __restrict__ x,
                                                         const float* __restrict__ W,
                                                         const int* __restrict__ edge_index,
                                                         const float* __restrict__ edge_time,
                                                         const float* __restrict__ node_time) {
    using namespace nvcuda;
    __shared__ __half xh[256 * 72];   // 36 KB
    __shared__ __half Wh[64 * 72];    //  9 KB
    int tid  = threadIdx.x;
    int warp = tid >> 5;
    int row0 = blockIdx.x * 256;

    // stage x tile first (16 float4/thread, front-batched for MLP)
    #pragma unroll 8
    for (int i = tid; i < 256 * 16; i += 256) {
        int r = i >> 4, c = (i & 15) * 4;
        if (row0 + r < TOTAL_ROWS) {
            float4 v = *(const float4*)(x + (size_t)(row0 + r) * DD + c);
            __half2* p = (__half2*)(xh + r * 72 + c);
            p[0] = __floats2half2_rn(v.x, v.y);
            p[1] = __floats2half2_rn(v.z, v.w);
        }
    }
    // stage W (64x64) as half, stride 72
    #pragma unroll
    for (int i = tid; i < 64 * 16; i += 256) {
        int r = i >> 4, c = (i & 15) * 4;
        float4 v = ((const float4*)W)[i];
        __half2* p = (__half2*)(Wh + r * 72 + c);
        p[0] = __floats2half2_rn(v.x, v.y);
        p[1] = __floats2half2_rn(v.z, v.w);
    }
    // fused partitioned degree count: 2 edges/thread (hides in load slack)
    int ei = blockIdx.x * 256 + tid;
    if (ei < E_EDGES / 2) {
        int2   d  = ((const int2*)(edge_index + E_EDGES))[ei];
        float2 et = ((const float2*)edge_time)[ei];
        int ta0 = compute_tact(et.x, node_time);
        int ta1 = compute_tact(et.y, node_time);
        if (ta0 < 8) atomicAdd(&g_ss.counts[d.x], 1);
        if (ta0 < 4) atomicAdd(&g_ss.cntA[d.x], 1);
        if (ta1 < 8) atomicAdd(&g_ss.counts[d.y], 1);
        if (ta1 < 4) atomicAdd(&g_ss.cntA[d.y], 1);
    }
    __syncthreads();

    #pragma unroll
    for (int h = 0; h < 2; h++) {
        int rloc = warp * 32 + h * 16;
        int r = row0 + rloc;
        if (r >= TOTAL_ROWS) break;

        wmma::fragment<wmma::accumulator, 16, 16, 16, float> acc[4];
        #pragma unroll
        for (int n = 0; n < 4; n++) wmma::fill_fragment(acc[n], 0.0f);

        #pragma unroll
        for (int k = 0; k < 4; k++) {
            wmma::fragment<wmma::matrix_a, 16, 16, 16, __half, wmma::row_major> af;
            wmma::load_matrix_sync(af, xh + rloc * 72 + k * 16, 72);
            #pragma unroll
            for (int n = 0; n < 4; n++) {
                wmma::fragment<wmma::matrix_b, 16, 16, 16, __half, wmma::row_major> bf;
                wmma::load_matrix_sync(bf, Wh + (k * 16) * 72 + n * 16, 72);
                wmma::mma_sync(acc[n], af, bf, acc[n]);
            }
        }

        // transposed store: input row r = t*N + node -> g_y[node*512 + t*64]
        int t = r / N_NODES;
        int node0 = r - t * N_NODES;
        __half* dst = g_y + (size_t)node0 * (T_STEPS * DD) + t * DD;
        #pragma unroll
        for (int n = 0; n < 4; n++) {
            wmma::fragment<wmma::accumulator, 16, 16, 16, __half> hacc;
            #pragma unroll
            for (int i = 0; i < hacc.num_elements; i++)
                hacc.x[i] = __float2half(acc[n].x[i]);
            wmma::store_matrix_sync(dst + n * 16, hacc, T_STEPS * DD, wmma::mem_row_major);
        }
    }
}

// ---------------------------------------------------------------------------
// Kernel 2: decoupled-lookback exclusive scan -> offsets, mid, cursors
__global__ __launch_bounds__(256) void scan_kernel() {
    __shared__ int wsum[8];
    __shared__ int base_s;
    int b = blockIdx.x, tid = threadIdx.x;
    int lane = tid & 31, wid = tid >> 5;
    int i = b * 256 + tid;
    int v = (i < N_NODES) ? g_ss.counts[i] : 0;

    int xi = v;
    #pragma unroll
    for (int o = 1; o < 32; o <<= 1) {
        int y = __shfl_up_sync(0xffffffffu, xi, o);
        if (lane >= o) xi += y;
    }
    if (lane == 31) wsum[wid] = xi;
    __syncthreads();
    if (tid == 0) {
        int a = 0;
        #pragma unroll
        for (int w = 0; w < 8; w++) { int t = wsum[w]; wsum[w] = a; a += t; }
    }
    __syncthreads();
    int excl = wsum[wid] + xi - v;

    if (tid == 255) {
        int total = excl + v;
        if (b == 0) {
            g_ss.pre[0] = total;
            __threadfence();
            atomicExch(&g_ss.flag[0], 2);
            base_s = 0;
        } else {
            g_ss.agg[b] = total;
            __threadfence();
            atomicExch(&g_ss.flag[b], 1);
            int base = 0;
            for (int j = b - 1; ; ) {
                int f;
                do { f = atomicAdd(&g_ss.flag[j], 0); } while (f == 0);
                if (f == 2) { base += atomicAdd(&g_ss.pre[j], 0); break; }
                base += atomicAdd(&g_ss.agg[j], 0);
                j--;
            }
            g_ss.pre[b] = base + total;
            __threadfence();
            atomicExch(&g_ss.flag[b], 2);
            base_s = base;
        }
        if (b == NPART - 1) g_offsets[N_NODES] = base_s + total;
    }
    __syncthreads();
    if (i < N_NODES) {
        int off = base_s + excl;
        int mid = off + g_ss.cntA[i];
        g_offsets[i] = off;
        g_mid[i]     = mid;
        g_curA[i]    = off;
        g_curB[i]    = mid;
    }
}

// ---------------------------------------------------------------------------
// Kernel 3: partitioned CSR fill; dead (tact==8) edges dropped.
__device__ __forceinline__ void fill_one(int e, const int* edge_index,
                                         const float* edge_time,
                                         const float* node_time,
                                         const float* edge_weight) {
    int   src = edge_index[e];
    int   dst = edge_index[E_EDGES + e];
    int  tact = compute_tact(edge_time[e], node_time);
    if (tact >= 8) return;
    int* cur = (tact < 4) ? &g_curA[dst] : &g_curB[dst];
    int pos = atomicAdd(cur, 1);
    g_edges[pos] = make_int2((src << 10) | tact, __float_as_int(edge_weight[e]));
}

__global__ void fill_kernel(const int* __restrict__ edge_index,
                            const float* __restrict__ edge_time,
                            const float* __restrict__ node_time,
                            const float* __restrict__ edge_weight) {
    int i = blockIdx.x * blockDim.x + threadIdx.x;
    if (i >= E_EDGES / 2) return;
    fill_one(i, edge_index, edge_time, node_time, edge_weight);
    fill_one(i + E_EDGES / 2, edge_index, edge_time, node_time, edge_weight);
}

// ---------------------------------------------------------------------------
// Kernel 4: gather. TWO warps per dst node.
// ALL y loads are UNCONDITIONAL (safe address: src is always a valid node);
// inactivity is handled by zeroing the weight. No predicated register merges
// -> fully renameable loads, pipelined loop, MLP ~8.
__device__ __forceinline__ unsigned long long pack2(float a, float b) {
    unsigned long long r;
    asm("mov.b64 %0, {%1, %2};" : "=l"(r) : "f"(a), "f"(b));
    return r;
}
__device__ __forceinline__ float2 unpack2(unsigned long long v) {
    float2 f;
    asm("mov.b64 {%0, %1}, %2;" : "=f"(f.x), "=f"(f.y) : "l"(v));
    return f;
}
__device__ __forceinline__ void ffma2(unsigned long long& acc, unsigned long long v,
                                      unsigned long long w) {
    asm("fma.rn.f32x2 %0, %1, %2, %0;" : "+l"(acc) : "l"(v), "l"(w));
}
__device__ __forceinline__ void mac8(unsigned long long acc[4], uint4 h, float w) {
    unsigned long long w2 = pack2(w, w);
    float2 f0 = __half22float2(*(const __half2*)&h.x);
    float2 f1 = __half22float2(*(const __half2*)&h.y);
    float2 f2 = __half22float2(*(const __half2*)&h.z);
    float2 f3 = __half22float2(*(const __half2*)&h.w);
    ffma2(acc[0], pack2(f0.x, f0.y), w2);
    ffma2(acc[1], pack2(f1.x, f1.y), w2);
    ffma2(acc[2], pack2(f2.x, f2.y), w2);
    ffma2(acc[3], pack2(f3.x, f3.y), w2);
}

// masked pass over [e, e1): unconditional loads, weight zeroed when t < tact
__device__ __forceinline__ void gather_masked(int e, int e1, int t, const char* ybase,
                                              unsigned long long acc[4]) {
    for (; e + 3 < e1; e += 4) {
        int2 m0 = g_edges[e];
        int2 m1 = g_edges[e + 1];
        int2 m2 = g_edges[e + 2];
        int2 m3 = g_edges[e + 3];
        uint4 h0 = *(const uint4*)(ybase + (size_t)(unsigned)(m0.x & 0xFFFFFC00));
        uint4 h1 = *(const uint4*)(ybase + (size_t)(unsigned)(m1.x & 0xFFFFFC00));
        uint4 h2 = *(const uint4*)(ybase + (size_t)(unsigned)(m2.x & 0xFFFFFC00));
        uint4 h3 = *(const uint4*)(ybase + (size_t)(unsigned)(m3.x & 0xFFFFFC00));
        float w0 = (t >= (m0.x & 15)) ? __int_as_float(m0.y) : 0.f;
        float w1 = (t >= (m1.x & 15)) ? __int_as_float(m1.y) : 0.f;
        float w2 = (t >= (m2.x & 15)) ? __int_as_float(m2.y) : 0.f;
        float w3 = (t >= (m3.x & 15)) ? __int_as_float(m3.y) : 0.f;
        mac8(acc, h0, w0);
        mac8(acc, h1, w1);
        mac8(acc, h2, w2);
        mac8(acc, h3, w3);
    }
    for (; e < e1; e++) {
        int2 m0 = g_edges[e];
        uint4 h0 = *(const uint4*)(ybase + (size_t)(unsigned)(m0.x & 0xFFFFFC00));
        float w0 = (t >= (m0.x & 15)) ? __int_as_float(m0.y) : 0.f;
        mac8(acc, h0, w0);
    }
}

// unconditional pass over [e, e1): every edge active (t >= 4 > any tact in A)
__device__ __forceinline__ void gather_uncond(int e, int e1, const char* ybase,
                                              unsigned long long acc[4]) {
    for (; e + 3 < e1; e += 4) {
        int2 m0 = g_edges[e];
        int2 m1 = g_edges[e + 1];
        int2 m2 = g_edges[e + 2];
        int2 m3 = g_edges[e + 3];
        uint4 h0 = *(const uint4*)(ybase + (size_t)(unsigned)(m0.x & 0xFFFFFC00));
        uint4 h1 = *(const uint4*)(ybase + (size_t)(unsigned)(m1.x & 0xFFFFFC00));
        uint4 h2 = *(const uint4*)(ybase + (size_t)(unsigned)(m2.x & 0xFFFFFC00));
        uint4 h3 = *(const uint4*)(ybase + (size_t)(unsigned)(m3.x & 0xFFFFFC00));
        mac8(acc, h0, __int_as_float(m0.y));
        mac8(acc, h1, __int_as_float(m1.y));
        mac8(acc, h2, __int_as_float(m2.y));
        mac8(acc, h3, __int_as_float(m3.y));
    }
    for (; e < e1; e++) {
        int2 m0 = g_edges[e];
        uint4 h0 = *(const uint4*)(ybase + (size_t)(unsigned)(m0.x & 0xFFFFFC00));
        mac8(acc, h0, __int_as_float(m0.y));
    }
}

__global__ __launch_bounds__(128) void gather_kernel(const float* __restrict__ bias,
                                                     float* __restrict__ out) {
    // re-zero scan/count state for the next replay (nothing here reads it)
    {
        int b = blockIdx.x;
        if (threadIdx.x < 2) {
            int i = b * 2 + threadIdx.x;
            g_ss.counts[i] = 0;
            g_ss.cntA[i]   = 0;
        }
        if (threadIdx.x == 2 && b < NPART) g_ss.flag[b] = 0;
    }

    int gw   = (blockIdx.x * 128 + threadIdx.x) >> 5;
    int lane = threadIdx.x & 31;
    if (gw >= 2 * N_NODES) return;
    int node  = gw >> 1;
    int group = gw & 1;
    int slot  = lane >> 3;          // 0..3
    int cg    = lane & 7;           // column group (16 B)
    int t     = group * 4 + slot;

    int off = g_offsets[node];
    int mid = g_mid[node];

    unsigned long long acc[4] = {0ull, 0ull, 0ull, 0ull};
    const char* ybase = (const char*)g_y + t * 128 + cg * 16;

    if (group == 0) {
        // region A only (t<4 never activates region B edges)
        gather_masked(off, mid, t, ybase, acc);
    } else {
        // region A: always active for t>=4
        gather_uncond(off, mid, ybase, acc);
        // region B: tact in 4..7, masked
        gather_masked(mid, g_offsets[node + 1], t, ybase, acc);
    }

    float4 b0 = *(const float4*)(bias + cg * 8);
    float4 b1 = *(const float4*)(bias + cg * 8 + 4);
    float2 v0 = unpack2(acc[0]);
    float2 v1 = unpack2(acc[1]);
    float2 v2 = unpack2(acc[2]);
    float2 v3 = unpack2(acc[3]);
    float* op = out + ((size_t)t * N_NODES + node) * DD + cg * 8;
    float4 o0, o1;
    o0.x = v0.x + b0.x; o0.y = v0.y + b0.y;
    o0.z = v1.x + b0.z; o0.w = v1.y + b0.w;
    o1.x = v2.x + b1.x; o1.y = v2.y + b1.y;
    o1.z = v3.x + b1.z; o1.w = v3.y + b1.w;
    *(float4*)op       = o0;
    *(float4*)(op + 4) = o1;
}

// ---------------------------------------------------------------------------
extern "C" void kernel_launch(void* const* d_in, const int* in_sizes, int n_in,
                              void* d_out, int out_size) {
    const float* x           = (const float*)d_in[0];   // [T, N, 64]
    const int*   edge_index  = (const int*)  d_in[1];   // [2, E]
    const float* edge_time   = (const float*)d_in[2];   // [E]
    const float* node_time   = (const float*)d_in[3];   // [T]
    const float* edge_weight = (const float*)d_in[4];   // [E]
    const float* W           = (const float*)d_in[5];   // [64, 64]
    const float* bias        = (const float*)d_in[6];   // [64]
    float* out = (float*)d_out;                         // [T, N, 64]

    // counts/cntA/flag start zeroed (static init) and are re-zeroed by
    // gather_kernel each run -> no memset node needed.

    // 1) y = x @ W (256 rows/block) + fused partitioned degree count
    gemm_count_kernel<<<(TOTAL_ROWS + 255) / 256, 256>>>(x, W, edge_index, edge_time, node_time);
    // 2) CSR offsets + mid + cursors
    scan_kernel<<<NPART, 256>>>();
    // 3) partitioned CSR fill (dead edges dropped)
    fill_kernel<<<(E_EDGES / 2 + 255) / 256, 256>>>(edge_index, edge_time, node_time, edge_weight);
    // 4) gather  [4th kernel -> ncu profile slot]
    gather_kernel<<<(2 * N_NODES + 3) / 4, 128>>>(bias, out);
}

// round 11
// speedup vs baseline: 1.0179x; 1.0179x over previous
#include <cuda_runtime.h>
#include <cuda_fp16.h>
#include <mma.h>

// Problem constants (fixed by the dataset)
#define T_STEPS 8
#define N_NODES 50000
#define E_EDGES 800000
#define DD 64
#define TOTAL_ROWS (T_STEPS * N_NODES)    // 400000
#define NPART ((N_NODES + 255) / 256)     // 196 scan blocks

// -------- scratch (static __device__ arrays; no allocation allowed) --------
// y laid out [node][t][64]  -> node stride = 1024 B; 8 t-rows contiguous.
__device__ __half g_y[(size_t)N_NODES * T_STEPS * DD];   // 51.2 MB
__device__ int    g_offsets[N_NODES + 1];
__device__ int    g_mid[N_NODES];       // off + #(tact<4)
__device__ int    g_curA[N_NODES];      // cursor for tact<4 region
__device__ int    g_curB[N_NODES];      // cursor for 4<=tact<8 region
__device__ int2   g_edges[E_EDGES];     // ((src<<10)|tact, w bits); dead edges dropped

struct ScanState {
    int counts[N_NODES];   // #(tact<8) per dst   (re-zeroed by gather_kernel)
    int cntA[N_NODES];     // #(tact<4) per dst   (re-zeroed by gather_kernel)
    int agg[NPART];
    int pre[NPART];
    int flag[NPART];       // 0=invalid, 1=aggregate, 2=prefix (re-zeroed by gather)
};
__device__ ScanState g_ss;

// ---------------------------------------------------------------------------
__device__ __forceinline__ int compute_tact(float et, const float* __restrict__ node_time) {
    int tact = 0;
    #pragma unroll
    for (int t = 0; t < T_STEPS; t++) tact += (__ldg(&node_time[t]) < et) ? 1 : 0;
    return tact;
}

// ---------------------------------------------------------------------------
// Kernel 1: y = x @ W via wmma, 256 rows/block (1563 blocks), fused counts.
__global__ __launch_bounds__(256) void gemm_count_kernel(const float* __restrict__ x,
                                                         const float* __restrict__ W,
                                                         const int* __restrict__ edge_index,
                                                         const float* __restrict__ edge_time,
                                                         const float* __restrict__ node_time) {
    using namespace nvcuda;
    __shared__ __half xh[256 * 72];   // 36 KB
    __shared__ __half Wh[64 * 72];    //  9 KB
    int tid  = threadIdx.x;
    int warp = tid >> 5;
    int row0 = blockIdx.x * 256;

    // stage x tile first (16 float4/thread, front-batched for MLP)
    #pragma unroll 8
    for (int i = tid; i < 256 * 16; i += 256) {
        int r = i >> 4, c = (i & 15) * 4;
        if (row0 + r < TOTAL_ROWS) {
            float4 v = *(const float4*)(x + (size_t)(row0 + r) * DD + c);
            __half2* p = (__half2*)(xh + r * 72 + c);
            p[0] = __floats2half2_rn(v.x, v.y);
            p[1] = __floats2half2_rn(v.z, v.w);
        }
    }
    // stage W (64x64) as half, stride 72
    #pragma unroll
    for (int i = tid; i < 64 * 16; i += 256) {
        int r = i >> 4, c = (i & 15) * 4;
        float4 v = ((const float4*)W)[i];
        __half2* p = (__half2*)(Wh + r * 72 + c);
        p[0] = __floats2half2_rn(v.x, v.y);
        p[1] = __floats2half2_rn(v.z, v.w);
    }
    // fused partitioned degree count: 2 edges/thread (hides in load slack)
    int ei = blockIdx.x * 256 + tid;
    if (ei < E_EDGES / 2) {
        int2   d  = ((const int2*)(edge_index + E_EDGES))[ei];
        float2 et = ((const float2*)edge_time)[ei];
        int ta0 = compute_tact(et.x, node_time);
        int ta1 = compute_tact(et.y, node_time);
        if (ta0 < 8) atomicAdd(&g_ss.counts[d.x], 1);
        if (ta0 < 4) atomicAdd(&g_ss.cntA[d.x], 1);
        if (ta1 < 8) atomicAdd(&g_ss.counts[d.y], 1);
        if (ta1 < 4) atomicAdd(&g_ss.cntA[d.y], 1);
    }
    __syncthreads();

    #pragma unroll
    for (int h = 0; h < 2; h++) {
        int rloc = warp * 32 + h * 16;
        int r = row0 + rloc;
        if (r >= TOTAL_ROWS) break;

        wmma::fragment<wmma::accumulator, 16, 16, 16, float> acc[4];
        #pragma unroll
        for (int n = 0; n < 4; n++) wmma::fill_fragment(acc[n], 0.0f);

        #pragma unroll
        for (int k = 0; k < 4; k++) {
            wmma::fragment<wmma::matrix_a, 16, 16, 16, __half, wmma::row_major> af;
            wmma::load_matrix_sync(af, xh + rloc * 72 + k * 16, 72);
            #pragma unroll
            for (int n = 0; n < 4; n++) {
                wmma::fragment<wmma::matrix_b, 16, 16, 16, __half, wmma::row_major> bf;
                wmma::load_matrix_sync(bf, Wh + (k * 16) * 72 + n * 16, 72);
                wmma::mma_sync(acc[n], af, bf, acc[n]);
            }
        }

        // transposed store: input row r = t*N + node -> g_y[node*512 + t*64]
        int t = r / N_NODES;
        int node0 = r - t * N_NODES;
        __half* dst = g_y + (size_t)node0 * (T_STEPS * DD) + t * DD;
        #pragma unroll
        for (int n = 0; n < 4; n++) {
            wmma::fragment<wmma::accumulator, 16, 16, 16, __half> hacc;
            #pragma unroll
            for (int i = 0; i < hacc.num_elements; i++)
                hacc.x[i] = __float2half(acc[n].x[i]);
            wmma::store_matrix_sync(dst + n * 16, hacc, T_STEPS * DD, wmma::mem_row_major);
        }
    }
}

// ---------------------------------------------------------------------------
// Kernel 2: decoupled-lookback exclusive scan -> offsets, mid, cursors
__global__ __launch_bounds__(256) void scan_kernel() {
    __shared__ int wsum[8];
    __shared__ int base_s;
    int b = blockIdx.x, tid = threadIdx.x;
    int lane = tid & 31, wid = tid >> 5;
    int i = b * 256 + tid;
    int v = (i < N_NODES) ? g_ss.counts[i] : 0;

    int xi = v;
    #pragma unroll
    for (int o = 1; o < 32; o <<= 1) {
        int y = __shfl_up_sync(0xffffffffu, xi, o);
        if (lane >= o) xi += y;
    }
    if (lane == 31) wsum[wid] = xi;
    __syncthreads();
    if (tid == 0) {
        int a = 0;
        #pragma unroll
        for (int w = 0; w < 8; w++) { int t = wsum[w]; wsum[w] = a; a += t; }
    }
    __syncthreads();
    int excl = wsum[wid] + xi - v;

    if (tid == 255) {
        int total = excl + v;
        if (b == 0) {
            g_ss.pre[0] = total;
            __threadfence();
            atomicExch(&g_ss.flag[0], 2);
            base_s = 0;
        } else {
            g_ss.agg[b] = total;
            __threadfence();
            atomicExch(&g_ss.flag[b], 1);
            int base = 0;
            for (int j = b - 1; ; ) {
                int f;
                do { f = atomicAdd(&g_ss.flag[j], 0); } while (f == 0);
                if (f == 2) { base += atomicAdd(&g_ss.pre[j], 0); break; }
                base += atomicAdd(&g_ss.agg[j], 0);
                j--;
            }
            g_ss.pre[b] = base + total;
            __threadfence();
            atomicExch(&g_ss.flag[b], 2);
            base_s = base;
        }
        if (b == NPART - 1) g_offsets[N_NODES] = base_s + total;
    }
    __syncthreads();
    if (i < N_NODES) {
        int off = base_s + excl;
        int mid = off + g_ss.cntA[i];
        g_offsets[i] = off;
        g_mid[i]     = mid;
        g_curA[i]    = off;
        g_curB[i]    = mid;
    }
}

// ---------------------------------------------------------------------------
// Kernel 3: partitioned CSR fill; dead (tact==8) edges dropped.
__device__ __forceinline__ void fill_one(int e, const int* edge_index,
                                         const float* edge_time,
                                         const float* node_time,
                                         const float* edge_weight) {
    int   src = edge_index[e];
    int   dst = edge_index[E_EDGES + e];
    int  tact = compute_tact(edge_time[e], node_time);
    if (tact >= 8) return;
    int* cur = (tact < 4) ? &g_curA[dst] : &g_curB[dst];
    int pos = atomicAdd(cur, 1);
    g_edges[pos] = make_int2((src << 10) | tact, __float_as_int(edge_weight[e]));
}

__global__ void fill_kernel(const int* __restrict__ edge_index,
                            const float* __restrict__ edge_time,
                            const float* __restrict__ node_time,
                            const float* __restrict__ edge_weight) {
    int i = blockIdx.x * blockDim.x + threadIdx.x;
    if (i >= E_EDGES / 2) return;
    fill_one(i, edge_index, edge_time, node_time, edge_weight);
    fill_one(i + E_EDGES / 2, edge_index, edge_time, node_time, edge_weight);
}

// ---------------------------------------------------------------------------
// Kernel 4: gather with HOMOGENEOUS blocks for load balance.
//  warp-units [0, N)      : HEAVY = node u, t=4..7 (uncond region A + pred B)
//  warp-units [N, 2N)     : LIGHT = node u-N, t=0..3 (pred region A)
// Blocks are all-heavy or all-light -> intra-block tail waste ~0; heavy blocks
// launch first so the grid tail is light.
__device__ __forceinline__ unsigned long long pack2(float a, float b) {
    unsigned long long r;
    asm("mov.b64 %0, {%1, %2};" : "=l"(r) : "f"(a), "f"(b));
    return r;
}
__device__ __forceinline__ float2 unpack2(unsigned long long v) {
    float2 f;
    asm("mov.b64 {%0, %1}, %2;" : "=f"(f.x), "=f"(f.y) : "l"(v));
    return f;
}
__device__ __forceinline__ void ffma2(unsigned long long& acc, unsigned long long v,
                                      unsigned long long w) {
    asm("fma.rn.f32x2 %0, %1, %2, %0;" : "+l"(acc) : "l"(v), "l"(w));
}
__device__ __forceinline__ void mac8(unsigned long long acc[4], uint4 h, float w) {
    unsigned long long w2 = pack2(w, w);
    float2 f0 = __half22float2(*(const __half2*)&h.x);
    float2 f1 = __half22float2(*(const __half2*)&h.y);
    float2 f2 = __half22float2(*(const __half2*)&h.z);
    float2 f3 = __half22float2(*(const __half2*)&h.w);
    ffma2(acc[0], pack2(f0.x, f0.y), w2);
    ffma2(acc[1], pack2(f1.x, f1.y), w2);
    ffma2(acc[2], pack2(f2.x, f2.y), w2);
    ffma2(acc[3], pack2(f3.x, f3.y), w2);
}

// predicated pass over [e, e1): active iff t >= (m.x & 15)
__device__ __forceinline__ void gather_pred(int e, int e1, int t, const char* ybase,
                                            unsigned long long acc[4]) {
    uint4 h0 = {0,0,0,0}, h1 = {0,0,0,0};
    for (; e + 1 < e1; e += 2) {
        int2 m0 = g_edges[e];
        int2 m1 = g_edges[e + 1];
        const char* p0 = ybase + (size_t)(unsigned)(m0.x & 0xFFFFFC00);
        const char* p1 = ybase + (size_t)(unsigned)(m1.x & 0xFFFFFC00);
        bool a0 = (t >= (m0.x & 15));
        bool a1 = (t >= (m1.x & 15));
        if (a0) h0 = *(const uint4*)p0;
        if (a1) h1 = *(const uint4*)p1;
        mac8(acc, h0, a0 ? __int_as_float(m0.y) : 0.f);
        mac8(acc, h1, a1 ? __int_as_float(m1.y) : 0.f);
    }
    if (e < e1) {
        int2 m0 = g_edges[e];
        const char* p0 = ybase + (size_t)(unsigned)(m0.x & 0xFFFFFC00);
        bool a0 = (t >= (m0.x & 15));
        if (a0) h0 = *(const uint4*)p0;
        mac8(acc, h0, a0 ? __int_as_float(m0.y) : 0.f);
    }
}

__global__ __launch_bounds__(128) void gather_kernel(const float* __restrict__ bias,
                                                     float* __restrict__ out) {
    // re-zero scan/count state for the next replay (nothing here reads it)
    {
        int b = blockIdx.x;
        if (threadIdx.x < 2) {
            int i = b * 2 + threadIdx.x;
            g_ss.counts[i] = 0;
            g_ss.cntA[i]   = 0;
        }
        if (threadIdx.x == 2 && b < NPART) g_ss.flag[b] = 0;
    }

    int gw   = (blockIdx.x * 128 + threadIdx.x) >> 5;
    int lane = threadIdx.x & 31;
    if (gw >= 2 * N_NODES) return;
    int heavy = (gw < N_NODES);
    int node  = heavy ? gw : gw - N_NODES;
    int slot  = lane >> 3;          // 0..3
    int cg    = lane & 7;           // column group (16 B)
    int t     = (heavy ? 4 : 0) + slot;

    int off = g_offsets[node];
    int mid = g_mid[node];

    unsigned long long acc[4] = {0ull, 0ull, 0ull, 0ull};
    const char* ybase = (const char*)g_y + t * 128 + cg * 16;

    if (!heavy) {
        // t in 0..3: only region A can be active; predicated
        gather_pred(off, mid, t, ybase, acc);
    } else {
        // region A: always active for t>=4 — unconditional, x4 unrolled
        int e = off;
        if ((e & 1) && e < mid) {            // align to 16B for int4 meta loads
            int2 m = g_edges[e++];
            uint4 h = *(const uint4*)(ybase + (size_t)(unsigned)(m.x & 0xFFFFFC00));
            mac8(acc, h, __int_as_float(m.y));
        }
        for (; e + 3 < mid; e += 4) {
            int4 ma = *(const int4*)&g_edges[e];       // edges e, e+1
            int4 mb = *(const int4*)&g_edges[e + 2];   // edges e+2, e+3
            uint4 h0 = *(const uint4*)(ybase + (size_t)(unsigned)(ma.x & 0xFFFFFC00));
            uint4 h1 = *(const uint4*)(ybase + (size_t)(unsigned)(ma.z & 0xFFFFFC00));
            uint4 h2 = *(const uint4*)(ybase + (size_t)(unsigned)(mb.x & 0xFFFFFC00));
            uint4 h3 = *(const uint4*)(ybase + (size_t)(unsigned)(mb.z & 0xFFFFFC00));
            mac8(acc, h0, __int_as_float(ma.y));
            mac8(acc, h1, __int_as_float(ma.w));
            mac8(acc, h2, __int_as_float(mb.y));
            mac8(acc, h3, __int_as_float(mb.w));
        }
        for (; e < mid; e++) {
            int2 m = g_edges[e];
            uint4 h = *(const uint4*)(ybase + (size_t)(unsigned)(m.x & 0xFFFFFC00));
            mac8(acc, h, __int_as_float(m.y));
        }
        // region B: tact in 4..7, predicated
        gather_pred(mid, g_offsets[node + 1], t, ybase, acc);
    }

    float4 b0 = *(const float4*)(bias + cg * 8);
    float4 b1 = *(const float4*)(bias + cg * 8 + 4);
    float2 v0 = unpack2(acc[0]);
    float2 v1 = unpack2(acc[1]);
    float2 v2 = unpack2(acc[2]);
    float2 v3 = unpack2(acc[3]);
    float* op = out + ((size_t)t * N_NODES + node) * DD + cg * 8;
    float4 o0, o1;
    o0.x = v0.x + b0.x; o0.y = v0.y + b0.y;
    o0.z = v1.x + b0.z; o0.w = v1.y + b0.w;
    o1.x = v2.x + b1.x; o1.y = v2.y + b1.y;
    o1.z = v3.x + b1.z; o1.w = v3.y + b1.w;
    *(float4*)op       = o0;
    *(float4*)(op + 4) = o1;
}

// ---------------------------------------------------------------------------
extern "C" void kernel_launch(void* const* d_in, const int* in_sizes, int n_in,
                              void* d_out, int out_size) {
    const float* x           = (const float*)d_in[0];   // [T, N, 64]
    const int*   edge_index  = (const int*)  d_in[1];   // [2, E]
    const float* edge_time   = (const float*)d_in[2];   // [E]
    const float* node_time   = (const float*)d_in[3];   // [T]
    const float* edge_weight = (const float*)d_in[4];   // [E]
    const float* W           = (const float*)d_in[5];   // [64, 64]
    const float* bias        = (const float*)d_in[6];   // [64]
    float* out = (float*)d_out;                         // [T, N, 64]

    // counts/cntA/flag start zeroed (static init) and are re-zeroed by
    // gather_kernel each run -> no memset node needed.

    // 1) y = x @ W (256 rows/block) + fused partitioned degree count
    gemm_count_kernel<<<(TOTAL_ROWS + 255) / 256, 256>>>(x, W, edge_index, edge_time, node_time);
    // 2) CSR offsets + mid + cursors
    scan_kernel<<<NPART, 256>>>();
    // 3) partitioned CSR fill (dead edges dropped)
    fill_kernel<<<(E_EDGES / 2 + 255) / 256, 256>>>(edge_index, edge_time, node_time, edge_weight);
    // 4) gather  [4th kernel -> ncu profile slot]
    gather_kernel<<<(2 * N_NODES + 3) / 4, 128>>>(bias, out);
}

// round 12
// speedup vs baseline: 1.1512x; 1.1309x over previous
#include <cuda_runtime.h>
#include <cuda_fp16.h>
#include <mma.h>

// Problem constants (fixed by the dataset)
#define T_STEPS 8
#define N_NODES 50000
#define E_EDGES 800000
#define DD 64
#define TOTAL_ROWS (T_STEPS * N_NODES)    // 400000
#define CAP 64                            // per-region slab capacity (Poisson(7.1) tail ~1e-40)

// -------- scratch (static __device__ arrays; no allocation allowed) --------
// y laid out [node][t][64]  -> node stride = 1024 B; 8 t-rows contiguous.
__device__ __half g_y[(size_t)N_NODES * T_STEPS * DD];          // 51.2 MB
// packed per-node counters: low 16 bits = region-A count (tact<4),
//                           high 16 bits = region-B count (4<=tact<8)
__device__ int    g_cnt[N_NODES];                                // zeroed by memset node
// per-node slab: [node*2*CAP .. +CAP) = region A, [+CAP .. +2*CAP) = region B
// entry = ((src<<10)|tact, weight bits)
__device__ int2   g_edges[(size_t)N_NODES * 2 * CAP];            // 51.2 MB

// ---------------------------------------------------------------------------
__device__ __forceinline__ int compute_tact(float et, const float* __restrict__ node_time) {
    int tact = 0;
    #pragma unroll
    for (int t = 0; t < T_STEPS; t++) tact += (__ldg(&node_time[t]) < et) ? 1 : 0;
    return tact;
}

__device__ __forceinline__ void place_edge(int src, int dst, float et, float w,
                                           const float* __restrict__ node_time) {
    int tact = compute_tact(et, node_time);
    if (tact >= 8) return;                       // dead edge: dropped
    bool regA = (tact < 4);
    int ret = atomicAdd(&g_cnt[dst], regA ? 1 : 0x10000);
    int pos = regA ? (ret & 0xFFFF) : (CAP + (ret >> 16));
    if (pos < 2 * CAP)                            // overflow guard (never fires)
        g_edges[(size_t)dst * (2 * CAP) + pos] =
            make_int2((src << 10) | tact, __float_as_int(w));
}

// ---------------------------------------------------------------------------
// Kernel 1: y = x @ W via wmma, 256 rows/block (1563 blocks).
// FUSED: full edge placement (tact + packed-atomic slot + slab store) — the
// latency of the atomics/stores hides in the GEMM's load slack (issue ~16%).
__global__ __launch_bounds__(256) void gemm_fill_kernel(const float* __restrict__ x,
                                                        const float* __restrict__ W,
                                                        const int* __restrict__ edge_index,
                                                        const float* __restrict__ edge_time,
                                                        const float* __restrict__ edge_weight,
                                                        const float* __restrict__ node_time) {
    using namespace nvcuda;
    __shared__ __half xh[256 * 72];   // 36 KB
    __shared__ __half Wh[64 * 72];    //  9 KB
    int tid  = threadIdx.x;
    int warp = tid >> 5;
    int row0 = blockIdx.x * 256;

    // stage x tile first (16 float4/thread, front-batched for MLP)
    #pragma unroll 8
    for (int i = tid; i < 256 * 16; i += 256) {
        int r = i >> 4, c = (i & 15) * 4;
        if (row0 + r < TOTAL_ROWS) {
            float4 v = *(const float4*)(x + (size_t)(row0 + r) * DD + c);
            __half2* p = (__half2*)(xh + r * 72 + c);
            p[0] = __floats2half2_rn(v.x, v.y);
            p[1] = __floats2half2_rn(v.z, v.w);
        }
    }
    // stage W (64x64) as half, stride 72 (conflict-free ldmatrix phases)
    #pragma unroll
    for (int i = tid; i < 64 * 16; i += 256) {
        int r = i >> 4, c = (i & 15) * 4;
        float4 v = ((const float4*)W)[i];
        __half2* p = (__half2*)(Wh + r * 72 + c);
        p[0] = __floats2half2_rn(v.x, v.y);
        p[1] = __floats2half2_rn(v.z, v.w);
    }
    // fused edge placement: 2 edges/thread (1563*256 >= E/2)
    int ei = blockIdx.x * 256 + tid;
    if (ei < E_EDGES / 2) {
        int2   s2 = ((const int2*)edge_index)[ei];              // src[2ei], src[2ei+1]
        int2   d2 = ((const int2*)(edge_index + E_EDGES))[ei];  // dst[2ei], dst[2ei+1]
        float2 et = ((const float2*)edge_time)[ei];
        float2 w2 = ((const float2*)edge_weight)[ei];
        place_edge(s2.x, d2.x, et.x, w2.x, node_time);
        place_edge(s2.y, d2.y, et.y, w2.y, node_time);
    }
    __syncthreads();

    #pragma unroll
    for (int h = 0; h < 2; h++) {
        int rloc = warp * 32 + h * 16;
        int r = row0 + rloc;
        if (r >= TOTAL_ROWS) break;

        wmma::fragment<wmma::accumulator, 16, 16, 16, float> acc[4];
        #pragma unroll
        for (int n = 0; n < 4; n++) wmma::fill_fragment(acc[n], 0.0f);

        #pragma unroll
        for (int k = 0; k < 4; k++) {
            wmma::fragment<wmma::matrix_a, 16, 16, 16, __half, wmma::row_major> af;
            wmma::load_matrix_sync(af, xh + rloc * 72 + k * 16, 72);
            #pragma unroll
            for (int n = 0; n < 4; n++) {
                wmma::fragment<wmma::matrix_b, 16, 16, 16, __half, wmma::row_major> bf;
                wmma::load_matrix_sync(bf, Wh + (k * 16) * 72 + n * 16, 72);
                wmma::mma_sync(acc[n], af, bf, acc[n]);
            }
        }

        // transposed store: input row r = t*N + node -> g_y[node*512 + t*64]
        // (50000 % 16 == 0 -> each 16-row fragment has uniform t)
        int t = r / N_NODES;
        int node0 = r - t * N_NODES;
        __half* dst = g_y + (size_t)node0 * (T_STEPS * DD) + t * DD;
        #pragma unroll
        for (int n = 0; n < 4; n++) {
            wmma::fragment<wmma::accumulator, 16, 16, 16, __half> hacc;
            #pragma unroll
            for (int i = 0; i < hacc.num_elements; i++)
                hacc.x[i] = __float2half(acc[n].x[i]);
            wmma::store_matrix_sync(dst + n * 16, hacc, T_STEPS * DD, wmma::mem_row_major);
        }
    }
}

// ---------------------------------------------------------------------------
// Kernel 2: gather with HOMOGENEOUS blocks (R11 bodies, slab addressing).
//  warp-units [0, N)  : HEAVY = node u, t=4..7 (uncond region A + pred B)
//  warp-units [N, 2N) : LIGHT = node u-N, t=0..3 (pred region A)
__device__ __forceinline__ unsigned long long pack2(float a, float b) {
    unsigned long long r;
    asm("mov.b64 %0, {%1, %2};" : "=l"(r) : "f"(a), "f"(b));
    return r;
}
__device__ __forceinline__ float2 unpack2(unsigned long long v) {
    float2 f;
    asm("mov.b64 {%0, %1}, %2;" : "=f"(f.x), "=f"(f.y) : "l"(v));
    return f;
}
__device__ __forceinline__ void ffma2(unsigned long long& acc, unsigned long long v,
                                      unsigned long long w) {
    asm("fma.rn.f32x2 %0, %1, %2, %0;" : "+l"(acc) : "l"(v), "l"(w));
}
__device__ __forceinline__ void mac8(unsigned long long acc[4], uint4 h, float w) {
    unsigned long long w2 = pack2(w, w);
    float2 f0 = __half22float2(*(const __half2*)&h.x);
    float2 f1 = __half22float2(*(const __half2*)&h.y);
    float2 f2 = __half22float2(*(const __half2*)&h.z);
    float2 f3 = __half22float2(*(const __half2*)&h.w);
    ffma2(acc[0], pack2(f0.x, f0.y), w2);
    ffma2(acc[1], pack2(f1.x, f1.y), w2);
    ffma2(acc[2], pack2(f2.x, f2.y), w2);
    ffma2(acc[3], pack2(f3.x, f3.y), w2);
}

// predicated pass over slab[0..n): active iff t >= (m.x & 15)
__device__ __forceinline__ void gather_pred(const int2* __restrict__ slab, int n, int t,
                                            const char* ybase, unsigned long long acc[4]) {
    uint4 h0 = {0,0,0,0}, h1 = {0,0,0,0};
    int e = 0;
    for (; e + 1 < n; e += 2) {
        int2 m0 = slab[e];
        int2 m1 = slab[e + 1];
        const char* p0 = ybase + (size_t)(unsigned)(m0.x & 0xFFFFFC00);
        const char* p1 = ybase + (size_t)(unsigned)(m1.x & 0xFFFFFC00);
        bool a0 = (t >= (m0.x & 15));
        bool a1 = (t >= (m1.x & 15));
        if (a0) h0 = *(const uint4*)p0;
        if (a1) h1 = *(const uint4*)p1;
        mac8(acc, h0, a0 ? __int_as_float(m0.y) : 0.f);
        mac8(acc, h1, a1 ? __int_as_float(m1.y) : 0.f);
    }
    if (e < n) {
        int2 m0 = slab[e];
        const char* p0 = ybase + (size_t)(unsigned)(m0.x & 0xFFFFFC00);
        bool a0 = (t >= (m0.x & 15));
        if (a0) h0 = *(const uint4*)p0;
        mac8(acc, h0, a0 ? __int_as_float(m0.y) : 0.f);
    }
}

__global__ __launch_bounds__(128) void gather_kernel(const float* __restrict__ bias,
                                                     float* __restrict__ out) {
    int gw   = (blockIdx.x * 128 + threadIdx.x) >> 5;
    int lane = threadIdx.x & 31;
    if (gw >= 2 * N_NODES) return;
    int heavy = (gw < N_NODES);
    int node  = heavy ? gw : gw - N_NODES;
    int slot  = lane >> 3;          // 0..3
    int cg    = lane & 7;           // column group (16 B)
    int t     = (heavy ? 4 : 0) + slot;

    int c  = g_cnt[node];
    int cA = c & 0xFFFF;
    int cB = c >> 16;
    if (cA > CAP) cA = CAP;         // overflow guard (never fires)
    if (cB > CAP) cB = CAP;
    const int2* slab = g_edges + (size_t)node * (2 * CAP);

    unsigned long long acc[4] = {0ull, 0ull, 0ull, 0ull};
    const char* ybase = (const char*)g_y + t * 128 + cg * 16;

    if (!heavy) {
        // t in 0..3: only region A can be active; predicated
        gather_pred(slab, cA, t, ybase, acc);
    } else {
        // region A: always active for t>=4 — unconditional, x4 unrolled,
        // slab base is 1024B-aligned so int4 pair loads are aligned
        int e = 0;
        for (; e + 3 < cA; e += 4) {
            int4 ma = *(const int4*)&slab[e];       // edges e, e+1
            int4 mb = *(const int4*)&slab[e + 2];   // edges e+2, e+3
            uint4 h0 = *(const uint4*)(ybase + (size_t)(unsigned)(ma.x & 0xFFFFFC00));
            uint4 h1 = *(const uint4*)(ybase + (size_t)(unsigned)(ma.z & 0xFFFFFC00));
            uint4 h2 = *(const uint4*)(ybase + (size_t)(unsigned)(mb.x & 0xFFFFFC00));
            uint4 h3 = *(const uint4*)(ybase + (size_t)(unsigned)(mb.z & 0xFFFFFC00));
            mac8(acc, h0, __int_as_float(ma.y));
            mac8(acc, h1, __int_as_float(ma.w));
            mac8(acc, h2, __int_as_float(mb.y));
            mac8(acc, h3, __int_as_float(mb.w));
        }
        for (; e < cA; e++) {
            int2 m = slab[e];
            uint4 h = *(const uint4*)(ybase + (size_t)(unsigned)(m.x & 0xFFFFFC00));
            mac8(acc, h, __int_as_float(m.y));
        }
        // region B: tact in 4..7, predicated
        gather_pred(slab + CAP, cB, t, ybase, acc);
    }

    float4 b0 = *(const float4*)(bias + cg * 8);
    float4 b1 = *(const float4*)(bias + cg * 8 + 4);
    float2 v0 = unpack2(acc[0]);
    float2 v1 = unpack2(acc[1]);
    float2 v2 = unpack2(acc[2]);
    float2 v3 = unpack2(acc[3]);
    float* op = out + ((size_t)t * N_NODES + node) * DD + cg * 8;
    float4 o0, o1;
    o0.x = v0.x + b0.x; o0.y = v0.y + b0.y;
    o0.z = v1.x + b0.z; o0.w = v1.y + b0.w;
    o1.x = v2.x + b1.x; o1.y = v2.y + b1.y;
    o1.z = v3.x + b1.z; o1.w = v3.y + b1.w;
    *(float4*)op       = o0;
    *(float4*)(op + 4) = o1;
}

// ---------------------------------------------------------------------------
extern "C" void kernel_launch(void* const* d_in, const int* in_sizes, int n_in,
                              void* d_out, int out_size) {
    const float* x           = (const float*)d_in[0];   // [T, N, 64]
    const int*   edge_index  = (const int*)  d_in[1];   // [2, E]
    const float* edge_time   = (const float*)d_in[2];   // [E]
    const float* node_time   = (const float*)d_in[3];   // [T]
    const float* edge_weight = (const float*)d_in[4];   // [E]
    const float* W           = (const float*)d_in[5];   // [64, 64]
    const float* bias        = (const float*)d_in[6];   // [64]
    float* out = (float*)d_out;                         // [T, N, 64]

    // zero the packed per-node counters (single graph-capturable memset node)
    void* cnt_ptr = nullptr;
    cudaGetSymbolAddress(&cnt_ptr, g_cnt);
    cudaMemsetAsync(cnt_ptr, 0, N_NODES * sizeof(int));

    // 1) y = x @ W (tensor cores) + fused slab edge placement (no scan needed)
    gemm_fill_kernel<<<(TOTAL_ROWS + 255) / 256, 256>>>(x, W, edge_index, edge_time,
                                                        edge_weight, node_time);
    // 2) gather
    gather_kernel<<<(2 * N_NODES + 3) / 4, 128>>>(bias, out);
}

// round 13
// speedup vs baseline: 1.1688x; 1.0153x over previous
#include <cuda_runtime.h>
#include <cuda_fp16.h>
#include <mma.h>

// Problem constants (fixed by the dataset)
#define T_STEPS 8
#define N_NODES 50000
#define E_EDGES 800000
#define DD 64
#define TOTAL_ROWS (T_STEPS * N_NODES)    // 400000
#define CAP 64                            // per-region slab capacity

// warp-units: [0, N) heavy (node u, t=4..7); [N, N + N/2) light (2 nodes, t=0..3)
#define N_UNITS (N_NODES + N_NODES / 2)   // 75000

// -------- scratch (static __device__ arrays; no allocation allowed) --------
// y laid out [node][t][64]  -> node stride = 1024 B; 8 t-rows contiguous.
__device__ __half g_y[(size_t)N_NODES * T_STEPS * DD];          // 51.2 MB
// packed per-node counters: low 16 = region-A count (tact<4), high 16 = region-B
__device__ int    g_cnt[N_NODES];                                // zeroed by memset node
// per-node slab: [node*2*CAP .. +CAP) = region A, [+CAP ..) = region B
__device__ int2   g_edges[(size_t)N_NODES * 2 * CAP];            // 51.2 MB

// ---------------------------------------------------------------------------
__device__ __forceinline__ int compute_tact(float et, const float* __restrict__ node_time) {
    int tact = 0;
    #pragma unroll
    for (int t = 0; t < T_STEPS; t++) tact += (__ldg(&node_time[t]) < et) ? 1 : 0;
    return tact;
}

__device__ __forceinline__ void place_edge(int src, int dst, float et, float w,
                                           const float* __restrict__ node_time) {
    int tact = compute_tact(et, node_time);
    if (tact >= 8) return;                       // dead edge: dropped
    bool regA = (tact < 4);
    int ret = atomicAdd(&g_cnt[dst], regA ? 1 : 0x10000);
    int pos = regA ? (ret & 0xFFFF) : (CAP + (ret >> 16));
    if (pos < 2 * CAP)                            // overflow guard (never fires)
        g_edges[(size_t)dst * (2 * CAP) + pos] =
            make_int2((src << 10) | tact, __float_as_int(w));
}

// ---------------------------------------------------------------------------
// Kernel 1: y = x @ W via wmma, 256 rows/block (1563 blocks), fused edge fill.
// Staging restructured for MLP: edge-stream loads issued first, then x loads
// in 2 batches of 8 back-to-back LDG.128 before any dependent convert/STS.
__global__ __launch_bounds__(256) void gemm_fill_kernel(const float* __restrict__ x,
                                                        const float* __restrict__ W,
                                                        const int* __restrict__ edge_index,
                                                        const float* __restrict__ edge_time,
                                                        const float* __restrict__ edge_weight,
                                                        const float* __restrict__ node_time) {
    using namespace nvcuda;
    __shared__ __half xh[256 * 72];   // 36 KB
    __shared__ __half Wh[64 * 72];    //  9 KB
    int tid  = threadIdx.x;
    int warp = tid >> 5;
    int row0 = blockIdx.x * 256;

    // edge-stream loads issued up front (independent of everything below)
    int ei = blockIdx.x * 256 + tid;
    bool do_edges = (ei < E_EDGES / 2);
    int2 s2 = {0, 0}, d2 = {0, 0};
    float2 et = {0.f, 0.f}, w2 = {0.f, 0.f};
    if (do_edges) {
        s2 = ((const int2*)edge_index)[ei];
        d2 = ((const int2*)(edge_index + E_EDGES))[ei];
        et = ((const float2*)edge_time)[ei];
        w2 = ((const float2*)edge_weight)[ei];
    }

    // stage x tile in 2 chunks: 8 batched LDG.128, then 8 convert+STS
    #pragma unroll
    for (int ch = 0; ch < 2; ch++) {
        float4 v[8];
        #pragma unroll
        for (int j = 0; j < 8; j++) {
            int i = tid + (ch * 8 + j) * 256;
            int r = i >> 4, c = (i & 15) * 4;
            size_t gr = row0 + r;
            if (gr >= TOTAL_ROWS) gr = TOTAL_ROWS - 1;   // clamp: row unused by MMA
            v[j] = *(const float4*)(x + gr * DD + c);
        }
        #pragma unroll
        for (int j = 0; j < 8; j++) {
            int i = tid + (ch * 8 + j) * 256;
            int r = i >> 4, c = (i & 15) * 4;
            __half2* p = (__half2*)(xh + r * 72 + c);
            p[0] = __floats2half2_rn(v[j].x, v[j].y);
            p[1] = __floats2half2_rn(v[j].z, v[j].w);
        }
    }
    // stage W (64x64) as half, stride 72 (conflict-free ldmatrix phases)
    #pragma unroll
    for (int i = tid; i < 64 * 16; i += 256) {
        int r = i >> 4, c = (i & 15) * 4;
        float4 v = ((const float4*)W)[i];
        __half2* p = (__half2*)(Wh + r * 72 + c);
        p[0] = __floats2half2_rn(v.x, v.y);
        p[1] = __floats2half2_rn(v.z, v.w);
    }
    // fused edge placement (atomics hide in load slack)
    if (do_edges) {
        place_edge(s2.x, d2.x, et.x, w2.x, node_time);
        place_edge(s2.y, d2.y, et.y, w2.y, node_time);
    }
    __syncthreads();

    #pragma unroll
    for (int h = 0; h < 2; h++) {
        int rloc = warp * 32 + h * 16;
        int r = row0 + rloc;
        if (r >= TOTAL_ROWS) break;

        wmma::fragment<wmma::accumulator, 16, 16, 16, float> acc[4];
        #pragma unroll
        for (int n = 0; n < 4; n++) wmma::fill_fragment(acc[n], 0.0f);

        #pragma unroll
        for (int k = 0; k < 4; k++) {
            wmma::fragment<wmma::matrix_a, 16, 16, 16, __half, wmma::row_major> af;
            wmma::load_matrix_sync(af, xh + rloc * 72 + k * 16, 72);
            #pragma unroll
            for (int n = 0; n < 4; n++) {
                wmma::fragment<wmma::matrix_b, 16, 16, 16, __half, wmma::row_major> bf;
                wmma::load_matrix_sync(bf, Wh + (k * 16) * 72 + n * 16, 72);
                wmma::mma_sync(acc[n], af, bf, acc[n]);
            }
        }

        // transposed store: input row r = t*N + node -> g_y[node*512 + t*64]
        int t = r / N_NODES;
        int node0 = r - t * N_NODES;
        __half* dst = g_y + (size_t)node0 * (T_STEPS * DD) + t * DD;
        #pragma unroll
        for (int n = 0; n < 4; n++) {
            wmma::fragment<wmma::accumulator, 16, 16, 16, __half> hacc;
            #pragma unroll
            for (int i = 0; i < hacc.num_elements; i++)
                hacc.x[i] = __float2half(acc[n].x[i]);
            wmma::store_matrix_sync(dst + n * 16, hacc, T_STEPS * DD, wmma::mem_row_major);
        }
    }
}

// ---------------------------------------------------------------------------
// Kernel 2: gather, balanced warp-units.
//  unit u in [0, N): HEAVY — node u, t=4..7 (uncond region A + pred region B)
//  unit u in [N, 1.5N): LIGHT — nodes 2(u-N), 2(u-N)+1, t=0..3 (pred region A)
// Expected visits/warp ~14.2 either way -> near-zero imbalance.
__device__ __forceinline__ unsigned long long pack2(float a, float b) {
    unsigned long long r;
    asm("mov.b64 %0, {%1, %2};" : "=l"(r) : "f"(a), "f"(b));
    return r;
}
__device__ __forceinline__ float2 unpack2(unsigned long long v) {
    float2 f;
    asm("mov.b64 {%0, %1}, %2;" : "=f"(f.x), "=f"(f.y) : "l"(v));
    return f;
}
__device__ __forceinline__ void ffma2(unsigned long long& acc, unsigned long long v,
                                      unsigned long long w) {
    asm("fma.rn.f32x2 %0, %1, %2, %0;" : "+l"(acc) : "l"(v), "l"(w));
}
__device__ __forceinline__ void mac8(unsigned long long acc[4], uint4 h, float w) {
    unsigned long long w2 = pack2(w, w);
    float2 f0 = __half22float2(*(const __half2*)&h.x);
    float2 f1 = __half22float2(*(const __half2*)&h.y);
    float2 f2 = __half22float2(*(const __half2*)&h.z);
    float2 f3 = __half22float2(*(const __half2*)&h.w);
    ffma2(acc[0], pack2(f0.x, f0.y), w2);
    ffma2(acc[1], pack2(f1.x, f1.y), w2);
    ffma2(acc[2], pack2(f2.x, f2.y), w2);
    ffma2(acc[3], pack2(f3.x, f3.y), w2);
}

// predicated pass over slab[0..n): active iff t >= (m.x & 15)
__device__ __forceinline__ void gather_pred(const int2* __restrict__ slab, int n, int t,
                                            const char* ybase, unsigned long long acc[4]) {
    uint4 h0 = {0,0,0,0}, h1 = {0,0,0,0};
    int e = 0;
    for (; e + 1 < n; e += 2) {
        int2 m0 = slab[e];
        int2 m1 = slab[e + 1];
        const char* p0 = ybase + (size_t)(unsigned)(m0.x & 0xFFFFFC00);
        const char* p1 = ybase + (size_t)(unsigned)(m1.x & 0xFFFFFC00);
        bool a0 = (t >= (m0.x & 15));
        bool a1 = (t >= (m1.x & 15));
        if (a0) h0 = *(const uint4*)p0;
        if (a1) h1 = *(const uint4*)p1;
        mac8(acc, h0, a0 ? __int_as_float(m0.y) : 0.f);
        mac8(acc, h1, a1 ? __int_as_float(m1.y) : 0.f);
    }
    if (e < n) {
        int2 m0 = slab[e];
        const char* p0 = ybase + (size_t)(unsigned)(m0.x & 0xFFFFFC00);
        bool a0 = (t >= (m0.x & 15));
        if (a0) h0 = *(const uint4*)p0;
        mac8(acc, h0, a0 ? __int_as_float(m0.y) : 0.f);
    }
}

__device__ __forceinline__ void write_out(float* __restrict__ out,
                                          const float* __restrict__ bias,
                                          const unsigned long long acc[4],
                                          int node, int t, int cg) {
    float4 b0 = *(const float4*)(bias + cg * 8);
    float4 b1 = *(const float4*)(bias + cg * 8 + 4);
    float2 v0 = unpack2(acc[0]);
    float2 v1 = unpack2(acc[1]);
    float2 v2 = unpack2(acc[2]);
    float2 v3 = unpack2(acc[3]);
    float* op = out + ((size_t)t * N_NODES + node) * DD + cg * 8;
    float4 o0, o1;
    o0.x = v0.x + b0.x; o0.y = v0.y + b0.y;
    o0.z = v1.x + b0.z; o0.w = v1.y + b0.w;
    o1.x = v2.x + b1.x; o1.y = v2.y + b1.y;
    o1.z = v3.x + b1.z; o1.w = v3.y + b1.w;
    *(float4*)op       = o0;
    *(float4*)(op + 4) = o1;
}

__global__ __launch_bounds__(128) void gather_kernel(const float* __restrict__ bias,
                                                     float* __restrict__ out) {
    int gw   = (blockIdx.x * 128 + threadIdx.x) >> 5;
    int lane = threadIdx.x & 31;
    if (gw >= N_UNITS) return;
    int slot = lane >> 3;           // 0..3
    int cg   = lane & 7;            // column group (16 B)

    if (gw < N_NODES) {
        // HEAVY: node gw, t = 4 + slot
        int node = gw;
        int t = 4 + slot;
        int c  = g_cnt[node];
        int cA = c & 0xFFFF;  if (cA > CAP) cA = CAP;
        int cB = c >> 16;     if (cB > CAP) cB = CAP;
        const int2* slab = g_edges + (size_t)node * (2 * CAP);

        unsigned long long acc[4] = {0ull, 0ull, 0ull, 0ull};
        const char* ybase = (const char*)g_y + t * 128 + cg * 16;

        // region A: always active for t>=4 — unconditional, x4 unrolled
        int e = 0;
        for (; e + 3 < cA; e += 4) {
            int4 ma = *(const int4*)&slab[e];
            int4 mb = *(const int4*)&slab[e + 2];
            uint4 h0 = *(const uint4*)(ybase + (size_t)(unsigned)(ma.x & 0xFFFFFC00));
            uint4 h1 = *(const uint4*)(ybase + (size_t)(unsigned)(ma.z & 0xFFFFFC00));
            uint4 h2 = *(const uint4*)(ybase + (size_t)(unsigned)(mb.x & 0xFFFFFC00));
            uint4 h3 = *(const uint4*)(ybase + (size_t)(unsigned)(mb.z & 0xFFFFFC00));
            mac8(acc, h0, __int_as_float(ma.y));
            mac8(acc, h1, __int_as_float(ma.w));
            mac8(acc, h2, __int_as_float(mb.y));
            mac8(acc, h3, __int_as_float(mb.w));
        }
        for (; e < cA; e++) {
            int2 m = slab[e];
            uint4 h = *(const uint4*)(ybase + (size_t)(unsigned)(m.x & 0xFFFFFC00));
            mac8(acc, h, __int_as_float(m.y));
        }
        // region B: tact in 4..7, predicated
        gather_pred(slab + CAP, cB, t, ybase, acc);
        write_out(out, bias, acc, node, t, cg);
    } else {
        // LIGHT: two nodes, t = slot
        int t = slot;
        int n0 = 2 * (gw - N_NODES);
        const char* ybase = (const char*)g_y + t * 128 + cg * 16;
        #pragma unroll
        for (int q = 0; q < 2; q++) {
            int node = n0 + q;
            int cA = g_cnt[node] & 0xFFFF;  if (cA > CAP) cA = CAP;
            const int2* slab = g_edges + (size_t)node * (2 * CAP);
            unsigned long long acc[4] = {0ull, 0ull, 0ull, 0ull};
            gather_pred(slab, cA, t, ybase, acc);
            write_out(out, bias, acc, node, t, cg);
        }
    }
}

// ---------------------------------------------------------------------------
extern "C" void kernel_launch(void* const* d_in, const int* in_sizes, int n_in,
                              void* d_out, int out_size) {
    const float* x           = (const float*)d_in[0];   // [T, N, 64]
    const int*   edge_index  = (const int*)  d_in[1];   // [2, E]
    const float* edge_time   = (const float*)d_in[2];   // [E]
    const float* node_time   = (const float*)d_in[3];   // [T]
    const float* edge_weight = (const float*)d_in[4];   // [E]
    const float* W           = (const float*)d_in[5];   // [64, 64]
    const float* bias        = (const float*)d_in[6];   // [64]
    float* out = (float*)d_out;                         // [T, N, 64]

    // zero the packed per-node counters (graph-capturable memset node)
    void* cnt_ptr = nullptr;
    cudaGetSymbolAddress(&cnt_ptr, g_cnt);
    cudaMemsetAsync(cnt_ptr, 0, N_NODES * sizeof(int));

    // 1) y = x @ W (tensor cores) + fused slab edge placement
    gemm_fill_kernel<<<(TOTAL_ROWS + 255) / 256, 256>>>(x, W, edge_index, edge_time,
                                                        edge_weight, node_time);
    // 2) gather (balanced warp-units)
    gather_kernel<<<(N_UNITS + 3) / 4, 128>>>(bias, out);
}